// round 1
// baseline (speedup 1.0000x reference)
#include <cuda_runtime.h>
#include <cuda_bf16.h>
#include <math.h>

#define D 128
#define MAXN 50000

// ---------------- scratch (no runtime allocation allowed) ----------------
__device__ float g_h[MAXN * D];      // node state
__device__ float g_m[MAXN * D];      // conv output (messages)
__device__ float g_agg[MAXN * D];    // aggregated messages
__device__ float g_gi[MAXN * 3 * D]; // input gates
__device__ float g_gh[MAXN * 3 * D]; // hidden gates

// ---------------- gather: h = embed[node_ids] ----------------
__global__ void gather_kernel(const int* __restrict__ node_ids,
                              const float4* __restrict__ embed4,
                              float4* __restrict__ h4, int N) {
    int idx = blockIdx.x * blockDim.x + threadIdx.x; // (n, chunk) chunk in [0,32)
    if (idx >= N * (D / 4)) return;
    int n = idx >> 5;
    int c = idx & 31;
    int id = node_ids[n];
    h4[(size_t)n * 32 + c] = embed4[(size_t)id * 32 + c];
}

// ---------------- GEMM: C[n][j] = bias[j] + sum_k A[n][k] * B'  ----------------
// transB=0: B is [K, M] row-major (C = A @ B)
// transB=1: B is [M, K] row-major (C = A @ B^T)
__global__ void gemm_kernel(const float* __restrict__ A,
                            const float* __restrict__ B,
                            const float* __restrict__ bias,
                            float* __restrict__ C,
                            int N, int M, int K, int transB) {
    __shared__ float As[32][33];
    __shared__ float Bs[32][33]; // Bs[k_local][j_local]
    int tx = threadIdx.x, ty = threadIdx.y;
    int row = blockIdx.y * 32 + ty;
    int col0 = blockIdx.x * 32;
    int col = col0 + tx;
    float acc = 0.0f;
    for (int k0 = 0; k0 < K; k0 += 32) {
        As[ty][tx] = (row < N) ? A[(size_t)row * K + k0 + tx] : 0.0f;
        if (transB) {
            int j = col0 + ty;
            Bs[tx][ty] = (j < M) ? B[(size_t)j * K + k0 + tx] : 0.0f;
        } else {
            Bs[ty][tx] = (col < M) ? B[(size_t)(k0 + ty) * M + col] : 0.0f;
        }
        __syncthreads();
#pragma unroll
        for (int kk = 0; kk < 32; kk++)
            acc += As[ty][kk] * Bs[kk][tx];
        __syncthreads();
    }
    if (row < N && col < M)
        C[(size_t)row * M + col] = acc + (bias ? bias[col] : 0.0f);
}

// ---------------- edge scatter: agg[dst] += m[src] ----------------
// one warp per edge; lane l handles 4 consecutive floats
__global__ void scatter_kernel(const float4* __restrict__ m4,
                               const int* __restrict__ src,
                               const int* __restrict__ dst,
                               float* __restrict__ agg, int E) {
    int warp = blockIdx.x * (blockDim.x >> 5) + (threadIdx.x >> 5);
    int lane = threadIdx.x & 31;
    if (warp >= E) return;
    int s = src[warp];
    int d = dst[warp];
    float4 v = m4[(size_t)s * 32 + lane];
    float* out = agg + (size_t)d * D + lane * 4;
    atomicAdd(out + 0, v.x);
    atomicAdd(out + 1, v.y);
    atomicAdd(out + 2, v.z);
    atomicAdd(out + 3, v.w);
}

// ---------------- GRU gate fusion ----------------
__global__ void gru_kernel(const float* __restrict__ gi,
                           const float* __restrict__ gh,
                           float* __restrict__ h, int N) {
    int idx = blockIdx.x * blockDim.x + threadIdx.x;
    if (idx >= N * D) return;
    int n = idx >> 7;
    int d = idx & (D - 1);
    const float* gin = gi + (size_t)n * 3 * D;
    const float* ghn = gh + (size_t)n * 3 * D;
    float ir = gin[d], iz = gin[d + D], in_ = gin[d + 2 * D];
    float hr = ghn[d], hz = ghn[d + D], hn = ghn[d + 2 * D];
    float r = 1.0f / (1.0f + __expf(-(ir + hr)));
    float z = 1.0f / (1.0f + __expf(-(iz + hz)));
    float nn = tanhf(in_ + r * hn);
    h[idx] = (1.0f - z) * nn + z * h[idx];
}

// ---------------- per-graph mean pool (batch sorted) ----------------
__device__ __forceinline__ int lower_bound_dev(const int* a, int n, int key) {
    int lo = 0, hi = n;
    while (lo < hi) {
        int mid = (lo + hi) >> 1;
        if (a[mid] < key) lo = mid + 1; else hi = mid;
    }
    return lo;
}

__global__ void pool_kernel(const float* __restrict__ h,
                            const int* __restrict__ batch,
                            float* __restrict__ out, int N) {
    int g = blockIdx.x;
    int d = threadIdx.x; // 128 threads
    __shared__ int s_lo, s_hi;
    if (d == 0) {
        s_lo = lower_bound_dev(batch, N, g);
        s_hi = lower_bound_dev(batch, N, g + 1);
    }
    __syncthreads();
    int lo = s_lo, hi = s_hi;
    float acc = 0.0f;
    for (int n = lo; n < hi; n++)
        acc += h[(size_t)n * D + d];
    float cnt = (float)(hi - lo);
    out[(size_t)g * D + d] = acc / fmaxf(cnt, 1.0f);
}

// ---------------- launch ----------------
extern "C" void kernel_launch(void* const* d_in, const int* in_sizes, int n_in,
                              void* d_out, int out_size) {
    const int* node_ids = (const int*)d_in[0];
    const int* edge_index = (const int*)d_in[1];
    const int* batch = (const int*)d_in[2];
    // d_in[3] = num_graphs scalar (derive G from out_size instead)
    const float* embed = (const float*)d_in[4];
    const float* conv_w = (const float*)d_in[5];  // [2, D, D]
    const float* w_ih = (const float*)d_in[6];    // [3D, D]
    const float* w_hh = (const float*)d_in[7];    // [3D, D]
    const float* b_ih = (const float*)d_in[8];
    const float* b_hh = (const float*)d_in[9];
    float* out = (float*)d_out;

    int N = in_sizes[0];
    int E = in_sizes[1] / 2;
    int G = out_size / D;
    const int* src = edge_index;
    const int* dst = edge_index + E;

    float *h, *m, *agg, *gi, *gh;
    cudaGetSymbolAddress((void**)&h, g_h);
    cudaGetSymbolAddress((void**)&m, g_m);
    cudaGetSymbolAddress((void**)&agg, g_agg);
    cudaGetSymbolAddress((void**)&gi, g_gi);
    cudaGetSymbolAddress((void**)&gh, g_gh);

    // h = embed[node_ids]
    {
        int total = N * (D / 4);
        gather_kernel<<<(total + 255) / 256, 256>>>(node_ids, (const float4*)embed,
                                                    (float4*)h, N);
    }

    dim3 gemmBlock(32, 32);
    int rowBlocks = (N + 31) / 32;

    for (int layer = 0; layer < 2; layer++) {
        // m = h @ conv_w[layer]   (B is [K=128, M=128], non-transposed)
        gemm_kernel<<<dim3(D / 32, rowBlocks), gemmBlock>>>(
            h, conv_w + (size_t)layer * D * D, nullptr, m, N, D, D, 0);

        // agg = 0
        cudaMemsetAsync(agg, 0, (size_t)N * D * sizeof(float), 0);

        // agg[dst] += m[src]
        {
            int warpsPerBlock = 8; // 256 threads
            int blocks = (E + warpsPerBlock - 1) / warpsPerBlock;
            scatter_kernel<<<blocks, warpsPerBlock * 32>>>((const float4*)m, src, dst,
                                                           agg, E);
        }

        // gi = agg @ w_ih^T + b_ih ; gh = h @ w_hh^T + b_hh
        gemm_kernel<<<dim3(3 * D / 32, rowBlocks), gemmBlock>>>(
            agg, w_ih, b_ih, gi, N, 3 * D, D, 1);
        gemm_kernel<<<dim3(3 * D / 32, rowBlocks), gemmBlock>>>(
            h, w_hh, b_hh, gh, N, 3 * D, D, 1);

        // h = GRU(gi, gh, h)
        {
            int total = N * D;
            gru_kernel<<<(total + 255) / 256, 256>>>(gi, gh, h, N);
        }
    }

    // mean pool per graph
    pool_kernel<<<G, D>>>(h, batch, out, N);
}

// round 2
// speedup vs baseline: 4.3637x; 4.3637x over previous
#include <cuda_runtime.h>
#include <cuda_bf16.h>
#include <math.h>

#define D 128
#define MAXN 50000

// ---------------- scratch (no runtime allocation allowed) ----------------
__device__ float g_h[MAXN * D];          // node state
__device__ float g_m[MAXN * D];          // conv output (messages)
__device__ float g_agg[MAXN * D];        // aggregated messages
__device__ float g_gi[MAXN * 3 * D];     // input gates
__device__ float g_gh[MAXN * 3 * D];     // hidden gates
__device__ float g_wihT[D * 3 * D];      // w_ih transposed -> [128, 384]
__device__ float g_whhT[D * 3 * D];      // w_hh transposed -> [128, 384]

// ---------------- weight transpose: WT[c][r] = W[r][c], W is [384,128] ----------------
__global__ void transpose_kernel(const float* __restrict__ W, float* __restrict__ WT) {
    int idx = blockIdx.x * blockDim.x + threadIdx.x;
    if (idx >= 3 * D * D) return;
    int r = idx / D;   // 0..383
    int c = idx % D;   // 0..127
    WT[(size_t)c * (3 * D) + r] = W[idx];
}

// ---------------- gather: h = embed[node_ids] ----------------
__global__ void gather_kernel(const int* __restrict__ node_ids,
                              const float4* __restrict__ embed4,
                              float4* __restrict__ h4, int N) {
    int idx = blockIdx.x * blockDim.x + threadIdx.x;
    if (idx >= N * (D / 4)) return;
    int n = idx >> 5;
    int c = idx & 31;
    int id = node_ids[n];
    h4[(size_t)n * 32 + c] = embed4[(size_t)id * 32 + c];
}

// ---------------- register-blocked GEMM ----------------
// C[N x M] = A[N x 128] @ B[128 x M] (+ bias), M a multiple of 128.
// Block tile 128x128, BK=16, 256 threads, each thread 8x8 outputs
// arranged as 2x2 chunks of 4, chunks separated by 64 (conflict-free LDS).
#define BK 16
__global__ __launch_bounds__(256, 2)
void gemm128(const float* __restrict__ A, const float* __restrict__ B,
             const float* __restrict__ bias, float* __restrict__ C,
             int N, int M) {
    __shared__ float As[BK][132];   // padded, stored transposed As[k][m]
    __shared__ float Bs[BK][128];   // Bs[k][n]

    int tid = threadIdx.x;
    int block_row = blockIdx.y * 128;
    int block_col = blockIdx.x * 128;

    // A tile loads: float4, 2 passes
    int aRow = tid >> 2;            // 0..63
    int aCol = (tid & 3) * 4;       // 0,4,8,12
    // B tile loads: float4, 2 passes
    int bRow = tid >> 5;            // 0..7
    int bCol = (tid & 31) * 4;      // 0..124

    int tr = (tid >> 4) * 4;        // 0..60
    int tc = (tid & 15) * 4;        // 0..60

    float acc[8][8];
#pragma unroll
    for (int i = 0; i < 8; i++)
#pragma unroll
        for (int j = 0; j < 8; j++) acc[i][j] = 0.0f;

    for (int k0 = 0; k0 < 128; k0 += BK) {
#pragma unroll
        for (int p = 0; p < 2; p++) {
            int r = aRow + p * 64;
            int gr = block_row + r;
            float4 v = make_float4(0.f, 0.f, 0.f, 0.f);
            if (gr < N) v = *(const float4*)(A + (size_t)gr * 128 + k0 + aCol);
            As[aCol + 0][r] = v.x;
            As[aCol + 1][r] = v.y;
            As[aCol + 2][r] = v.z;
            As[aCol + 3][r] = v.w;
        }
#pragma unroll
        for (int p = 0; p < 2; p++) {
            int r = bRow + p * 8;
            float4 v = *(const float4*)(B + (size_t)(k0 + r) * M + block_col + bCol);
            *(float4*)&Bs[r][bCol] = v;
        }
        __syncthreads();

#pragma unroll
        for (int k = 0; k < BK; k++) {
            float4 m0 = *(const float4*)&As[k][tr];
            float4 m1 = *(const float4*)&As[k][tr + 64];
            float4 n0 = *(const float4*)&Bs[k][tc];
            float4 n1 = *(const float4*)&Bs[k][tc + 64];
            float rm[8] = {m0.x, m0.y, m0.z, m0.w, m1.x, m1.y, m1.z, m1.w};
            float rn[8] = {n0.x, n0.y, n0.z, n0.w, n1.x, n1.y, n1.z, n1.w};
#pragma unroll
            for (int i = 0; i < 8; i++)
#pragma unroll
                for (int j = 0; j < 8; j++)
                    acc[i][j] = fmaf(rm[i], rn[j], acc[i][j]);
        }
        __syncthreads();
    }

    // bias
    float bx[8] = {0, 0, 0, 0, 0, 0, 0, 0};
    if (bias) {
#pragma unroll
        for (int jj = 0; jj < 2; jj++) {
            float4 b = *(const float4*)(bias + block_col + tc + jj * 64);
            bx[jj * 4 + 0] = b.x; bx[jj * 4 + 1] = b.y;
            bx[jj * 4 + 2] = b.z; bx[jj * 4 + 3] = b.w;
        }
    }

#pragma unroll
    for (int ii = 0; ii < 2; ii++) {
#pragma unroll
        for (int i = 0; i < 4; i++) {
            int row = block_row + tr + ii * 64 + i;
            if (row >= N) continue;
#pragma unroll
            for (int jj = 0; jj < 2; jj++) {
                int col = block_col + tc + jj * 64;
                float4 r;
                r.x = acc[ii * 4 + i][jj * 4 + 0] + bx[jj * 4 + 0];
                r.y = acc[ii * 4 + i][jj * 4 + 1] + bx[jj * 4 + 1];
                r.z = acc[ii * 4 + i][jj * 4 + 2] + bx[jj * 4 + 2];
                r.w = acc[ii * 4 + i][jj * 4 + 3] + bx[jj * 4 + 3];
                *(float4*)&C[(size_t)row * M + col] = r;
            }
        }
    }
}

// ---------------- edge scatter: agg[dst] += m[src], one warp per edge ----------------
__global__ void scatter_kernel(const float4* __restrict__ m4,
                               const int* __restrict__ src,
                               const int* __restrict__ dst,
                               float* __restrict__ agg, int E) {
    int e = blockIdx.x * (blockDim.x >> 5) + (threadIdx.x >> 5);
    int lane = threadIdx.x & 31;
    if (e >= E) return;
    int s = __ldg(&src[e]);
    int d = __ldg(&dst[e]);
    float4 v = m4[(size_t)s * 32 + lane];
    float* p = agg + (size_t)d * D + lane * 4;
    asm volatile("red.global.add.v4.f32 [%0], {%1, %2, %3, %4};"
                 :: "l"(p), "f"(v.x), "f"(v.y), "f"(v.z), "f"(v.w)
                 : "memory");
}

// ---------------- GRU gate fusion (vectorized) ----------------
__global__ void gru_kernel(const float4* __restrict__ gi4,
                           const float4* __restrict__ gh4,
                           float4* __restrict__ h4, int total4) {
    int idx = blockIdx.x * blockDim.x + threadIdx.x;
    if (idx >= total4) return;
    int n = idx >> 5;
    int c = idx & 31;
    const float4* gin = gi4 + (size_t)n * 96;
    const float4* ghn = gh4 + (size_t)n * 96;
    float4 ir = gin[c], iz = gin[c + 32], in_ = gin[c + 64];
    float4 hr = ghn[c], hz = ghn[c + 32], hn = ghn[c + 64];
    float4 h = h4[idx];
    float4 o;
#define GRU1(X, IR, IZ, IN, HR, HZ, HN, H)                         \
    {                                                              \
        float r = 1.0f / (1.0f + __expf(-((IR) + (HR))));          \
        float z = 1.0f / (1.0f + __expf(-((IZ) + (HZ))));          \
        float nn = tanhf((IN) + r * (HN));                         \
        o.X = (1.0f - z) * nn + z * (H);                           \
    }
    GRU1(x, ir.x, iz.x, in_.x, hr.x, hz.x, hn.x, h.x)
    GRU1(y, ir.y, iz.y, in_.y, hr.y, hz.y, hn.y, h.y)
    GRU1(z, ir.z, iz.z, in_.z, hr.z, hz.z, hn.z, h.z)
    GRU1(w, ir.w, iz.w, in_.w, hr.w, hz.w, hn.w, h.w)
#undef GRU1
    h4[idx] = o;
}

// ---------------- per-graph mean pool (batch sorted) ----------------
__device__ __forceinline__ int lower_bound_dev(const int* a, int n, int key) {
    int lo = 0, hi = n;
    while (lo < hi) {
        int mid = (lo + hi) >> 1;
        if (a[mid] < key) lo = mid + 1; else hi = mid;
    }
    return lo;
}

__global__ void pool_kernel(const float* __restrict__ h,
                            const int* __restrict__ batch,
                            float* __restrict__ out, int N) {
    int g = blockIdx.x;
    int tid = threadIdx.x;           // 512 threads
    int sub = tid >> 7;              // 0..3
    int d = tid & 127;
    __shared__ int s_lo, s_hi;
    __shared__ float sbuf[4][128];
    if (tid == 0) {
        s_lo = lower_bound_dev(batch, N, g);
        s_hi = lower_bound_dev(batch, N, g + 1);
    }
    __syncthreads();
    int lo = s_lo, hi = s_hi;
    float acc = 0.0f;
    for (int n = lo + sub; n < hi; n += 4)
        acc += h[(size_t)n * D + d];
    sbuf[sub][d] = acc;
    __syncthreads();
    if (sub == 0) {
        float total = sbuf[0][d] + sbuf[1][d] + sbuf[2][d] + sbuf[3][d];
        float cnt = (float)(hi - lo);
        out[(size_t)g * D + d] = total / fmaxf(cnt, 1.0f);
    }
}

// ---------------- launch ----------------
extern "C" void kernel_launch(void* const* d_in, const int* in_sizes, int n_in,
                              void* d_out, int out_size) {
    const int* node_ids = (const int*)d_in[0];
    const int* edge_index = (const int*)d_in[1];
    const int* batch = (const int*)d_in[2];
    const float* embed = (const float*)d_in[4];
    const float* conv_w = (const float*)d_in[5];  // [2, D, D]
    const float* w_ih = (const float*)d_in[6];    // [3D, D]
    const float* w_hh = (const float*)d_in[7];    // [3D, D]
    const float* b_ih = (const float*)d_in[8];
    const float* b_hh = (const float*)d_in[9];
    float* out = (float*)d_out;

    int N = in_sizes[0];
    int E = in_sizes[1] / 2;
    int G = out_size / D;
    const int* src = edge_index;
    const int* dst = edge_index + E;

    float *h, *m, *agg, *gi, *gh, *wihT, *whhT;
    cudaGetSymbolAddress((void**)&h, g_h);
    cudaGetSymbolAddress((void**)&m, g_m);
    cudaGetSymbolAddress((void**)&agg, g_agg);
    cudaGetSymbolAddress((void**)&gi, g_gi);
    cudaGetSymbolAddress((void**)&gh, g_gh);
    cudaGetSymbolAddress((void**)&wihT, g_wihT);
    cudaGetSymbolAddress((void**)&whhT, g_whhT);

    // transpose gate weights once (cheap, part of graph)
    transpose_kernel<<<(3 * D * D + 255) / 256, 256>>>(w_ih, wihT);
    transpose_kernel<<<(3 * D * D + 255) / 256, 256>>>(w_hh, whhT);

    // h = embed[node_ids]
    gather_kernel<<<(N * 32 + 255) / 256, 256>>>(node_ids, (const float4*)embed,
                                                 (float4*)h, N);

    int rowBlocks = (N + 127) / 128;

    for (int layer = 0; layer < 2; layer++) {
        // m = h @ conv_w[layer]
        gemm128<<<dim3(1, rowBlocks), 256>>>(h, conv_w + (size_t)layer * D * D,
                                             nullptr, m, N, D);

        // agg = 0
        cudaMemsetAsync(agg, 0, (size_t)N * D * sizeof(float), 0);

        // agg[dst] += m[src]
        {
            int warpsPerBlock = 8; // 256 threads
            int blocks = (E + warpsPerBlock - 1) / warpsPerBlock;
            scatter_kernel<<<blocks, warpsPerBlock * 32>>>((const float4*)m, src, dst,
                                                           agg, E);
        }

        // gi = agg @ wihT + b_ih ; gh = h @ whhT + b_hh
        gemm128<<<dim3(3, rowBlocks), 256>>>(agg, wihT, b_ih, gi, N, 3 * D);
        gemm128<<<dim3(3, rowBlocks), 256>>>(h, whhT, b_hh, gh, N, 3 * D);

        // h = GRU(gi, gh, h)
        gru_kernel<<<(N * 32 + 255) / 256, 256>>>((const float4*)gi,
                                                  (const float4*)gh,
                                                  (float4*)h, N * 32);
    }

    // mean pool per graph
    pool_kernel<<<G, 512>>>(h, batch, out, N);
}